// round 3
// baseline (speedup 1.0000x reference)
#include <cuda_runtime.h>
#include <math.h>

#define NN 2048
#define DD 128

__constant__ int c_xidx[4] = {4, 9, 14, 19};
__constant__ int c_eidx[4] = {0, 4, 9, 14};

// ---------------- static device scratch ----------------
__device__ unsigned d_bitmask[4][NN][64];     // mask bitmaps per step
__device__ float    d_Wh[4][NN][DD];          // per-gate projected features
__device__ float4   d_rowinfo[4][NN];         // {-s_src, exp(s_src), exp(a*s_src), 0}
__device__ float4   d_colinfo[4][NN];         // { s_dst, exp(s_dst), exp(a*s_dst), 0}
__device__ float    d_gates[4][NN * DD];      // elu(attn@Wh) per gate
__device__ float    d_cell[NN * DD];
__device__ float    d_hidden[NN * DD];
__device__ float    d_outs[4][NN * DD];       // sigmoid(hidden@W+b) per step [t][n][c]
__device__ float    d_y1[3][NN * DD];
__device__ float    d_y2[2][NN * DD];
__device__ float    d_convwT[3][256][DD];     // conv weights: [l][s*128+c][o]

// ---------------- packed f32x2 helpers ----------------
__device__ __forceinline__ void lds_v2u64(unsigned long long& a, unsigned long long& b,
                                          unsigned addr) {
    asm volatile("ld.shared.v2.u64 {%0,%1},[%2];" : "=l"(a), "=l"(b) : "r"(addr));
}
__device__ __forceinline__ void ffma2(unsigned long long& d, unsigned long long a,
                                      unsigned long long b) {
    asm volatile("fma.rn.f32x2 %0, %1, %2, %0;" : "+l"(d) : "l"(a), "l"(b));
}
__device__ __forceinline__ void unpack2(float& lo, float& hi, unsigned long long v) {
    unsigned l, h;
    asm("mov.b64 {%0,%1}, %2;" : "=r"(l), "=r"(h) : "l"(v));
    lo = __uint_as_float(l);
    hi = __uint_as_float(h);
}

// ---------------- init: cell = actors[:,0,:], hidden = h0 ----------------
__global__ void k_init(const float* __restrict__ actors, const float* __restrict__ h0) {
    int idx = blockIdx.x * blockDim.x + threadIdx.x;
    if (idx >= NN * DD) return;
    int n = idx >> 7, dd = idx & 127;
    d_cell[idx]   = actors[(size_t)n * 20 * DD + dd];
    d_hidden[idx] = h0[dd];
}

// ---------------- pack adjacency slices into bitmasks (all 4 steps) ----------------
__global__ void k_pack(const int* __restrict__ G) {
    int wid  = (blockIdx.x * blockDim.x + threadIdx.x) >> 5;
    int lane = threadIdx.x & 31;
    int word = wid & 63;
    int n    = (wid >> 6) & (NN - 1);
    int t    = wid >> 17;
    int e    = c_eidx[t];
    int m    = (word << 5) + lane;
    int v    = G[(size_t)n * 20 * NN + (size_t)e * NN + m];
    unsigned b = __ballot_sync(0xffffffffu, v > 0);
    if (lane == 0) d_bitmask[t][n][word] = b;
}

// ---------------- transpose conv weights ----------------
__global__ void k_transposeW(const float* __restrict__ convw) {
    int idx = blockIdx.x * blockDim.x + threadIdx.x;
    if (idx >= 3 * 256 * DD) return;
    int o = idx & 127;
    int k = (idx >> 7) & 255;
    int l = idx >> 15;
    int c = k & 127, s = k >> 7;
    d_convwT[l][k][o] = convw[(((size_t)l * 128 + o) * 128 + c) * 2 + s];
}

// ---------------- Wh = [X_t | hidden] @ Wg ----------------
__global__ __launch_bounds__(256) void k_wh(const float* __restrict__ actors,
                                            const float* __restrict__ Wg, int t) {
    __shared__ __align__(16) float As[16][68];
    __shared__ __align__(16) float Bs[16][68];
    int tid = threadIdx.x;
    int n0  = blockIdx.x * 64;
    int g   = blockIdx.y >> 1;
    int d0  = (blockIdx.y & 1) * 64;
    int tx  = tid & 15, ty = tid >> 4;
    float acc[4][4] = {};
    int xoff = c_xidx[t] * DD;
    int la_n = tid >> 2;
    int la_k = (tid & 3) * 4;
    int lb_k = tid >> 4;
    int lb_d = (tid & 15) * 4;
    for (int k0 = 0; k0 < 256; k0 += 16) {
        __syncthreads();
        int f = k0 + la_k;
        float4 av;
        if (f < 128) av = *(const float4*)&actors[(size_t)(n0 + la_n) * 2560 + xoff + f];
        else         av = *(const float4*)&d_hidden[(n0 + la_n) * DD + f - 128];
        As[la_k + 0][la_n] = av.x; As[la_k + 1][la_n] = av.y;
        As[la_k + 2][la_n] = av.z; As[la_k + 3][la_n] = av.w;
        *(float4*)&Bs[lb_k][lb_d] =
            *(const float4*)&Wg[((size_t)g * 256 + k0 + lb_k) * DD + d0 + lb_d];
        __syncthreads();
#pragma unroll
        for (int kk = 0; kk < 16; kk++) {
            float4 a = *(float4*)&As[kk][ty * 4];
            float4 b = *(float4*)&Bs[kk][tx * 4];
            float ar[4] = {a.x, a.y, a.z, a.w};
            float br[4] = {b.x, b.y, b.z, b.w};
#pragma unroll
            for (int i = 0; i < 4; i++)
#pragma unroll
                for (int j = 0; j < 4; j++) acc[i][j] = fmaf(ar[i], br[j], acc[i][j]);
        }
    }
#pragma unroll
    for (int i = 0; i < 4; i++) {
        int row = n0 + ty * 4 + i;
        float4 o = make_float4(acc[i][0], acc[i][1], acc[i][2], acc[i][3]);
        *(float4*)&d_Wh[g][row][d0 + tx * 4] = o;
    }
}

// ---------------- per-(g,n) scores + factorized exps ----------------
__global__ void k_prep(const float* __restrict__ ag) {
    int gid  = (blockIdx.x * blockDim.x + threadIdx.x) >> 5;
    int lane = threadIdx.x & 31;
    int g = gid >> 11, n = gid & 2047;
    float4 wv = *(const float4*)&d_Wh[g][n][lane * 4];
    float4 as = *(const float4*)&ag[g * 256 + lane * 4];
    float4 ad = *(const float4*)&ag[g * 256 + 128 + lane * 4];
    float s1 = wv.x * as.x + wv.y * as.y + wv.z * as.z + wv.w * as.w;
    float s2 = wv.x * ad.x + wv.y * ad.y + wv.z * ad.z + wv.w * ad.w;
#pragma unroll
    for (int off = 16; off; off >>= 1) {
        s1 += __shfl_xor_sync(0xffffffffu, s1, off);
        s2 += __shfl_xor_sync(0xffffffffu, s2, off);
    }
    if (lane == 0) {
        d_rowinfo[g][n] = make_float4(-s1, expf(s1), expf(0.2f * s1), 0.f);
        d_colinfo[g][n] = make_float4(s2, expf(s2), expf(0.2f * s2), 0.f);
    }
}

__device__ __forceinline__ float eluf(float x) { return x > 0.f ? x : expm1f(x); }

// ---------------- attention + elu (FFMA2 version) ----------------
// Block: 4 warps; each warp owns 8 rows (full 128 dims, 4 per lane as 2 f32x2).
// m chunked by 32. Coefs stored duplicated {cf,cf} for direct packed operands.
__global__ __launch_bounds__(128) void k_attn(int t) {
    __shared__ __align__(16) float  sWh[32 * DD];      // 16 KB
    __shared__ __align__(16) float4 sCol[32];          // 512 B
    __shared__ __align__(16) float2 sCoef[4][32][8];   // 8 KB  [warp][j][row] dup pairs
    const int g    = blockIdx.y;
    const int warp = threadIdx.x >> 5;
    const int lane = threadIdx.x & 31;
    const int tid  = threadIdx.x;
    const int n0   = blockIdx.x * 32 + warp * 8;

    float thr[8], A1[8], A2[8];
#pragma unroll
    for (int r = 0; r < 8; r++) {
        float4 ri = d_rowinfo[g][n0 + r];
        thr[r] = ri.x; A1[r] = ri.y; A2[r] = ri.z;
    }
    const unsigned* bm0 = &d_bitmask[t][n0][0];   // 8 rows, stride 64 words
    const float* Whg = &d_Wh[g][0][0];

    unsigned long long acc[8][2] = {};
    float den[8] = {};

    const unsigned sWh_base  = (unsigned)__cvta_generic_to_shared(sWh);
    const unsigned sCoef_base = (unsigned)__cvta_generic_to_shared(&sCoef[warp][0][0]);
    const unsigned vlane = sWh_base + lane * 16;

    for (int m0 = 0; m0 < NN; m0 += 32) {
        __syncthreads();
        {
            const float4* src = (const float4*)(Whg + m0 * DD);
            float4* dst = (float4*)sWh;
#pragma unroll
            for (int i = 0; i < 8; i++) dst[tid + 128 * i] = src[tid + 128 * i];
            if (tid < 32) sCol[tid] = d_colinfo[g][m0 + tid];
        }
        __syncthreads();

        // coefficients for this warp's 8 rows at m = m0 + lane
        {
            float4 ci = sCol[lane];
            int wbase = m0 >> 5;
#pragma unroll
            for (int r = 0; r < 8; r++) {
                unsigned w = bm0[r * 64 + wbase];
                bool act = (w >> lane) & 1u;
                float cf = (ci.x >= thr[r]) ? A1[r] * ci.y : A2[r] * ci.z;
                cf = act ? cf : 0.f;
                den[r] += cf;
                sCoef[warp][lane][r] = make_float2(cf, cf);
            }
        }
        __syncwarp();

        // dense body: acc[r] += coef[r][j] (packed) * Wh[j][d-pair]
#pragma unroll
        for (int j = 0; j < 32; j++) {
            unsigned long long v0, v1;
            lds_v2u64(v0, v1, vlane + j * 512);
            unsigned caddr = sCoef_base + j * 64;
            unsigned long long c0, c1, c2, c3, c4, c5, c6, c7;
            lds_v2u64(c0, c1, caddr);
            lds_v2u64(c2, c3, caddr + 16);
            lds_v2u64(c4, c5, caddr + 32);
            lds_v2u64(c6, c7, caddr + 48);
            ffma2(acc[0][0], c0, v0); ffma2(acc[0][1], c0, v1);
            ffma2(acc[1][0], c1, v0); ffma2(acc[1][1], c1, v1);
            ffma2(acc[2][0], c2, v0); ffma2(acc[2][1], c2, v1);
            ffma2(acc[3][0], c3, v0); ffma2(acc[3][1], c3, v1);
            ffma2(acc[4][0], c4, v0); ffma2(acc[4][1], c4, v1);
            ffma2(acc[5][0], c5, v0); ffma2(acc[5][1], c5, v1);
            ffma2(acc[6][0], c6, v0); ffma2(acc[6][1], c6, v1);
            ffma2(acc[7][0], c7, v0); ffma2(acc[7][1], c7, v1);
        }
    }

    // reduce denominators across lanes
#pragma unroll
    for (int r = 0; r < 8; r++) {
#pragma unroll
        for (int off = 16; off; off >>= 1)
            den[r] += __shfl_xor_sync(0xffffffffu, den[r], off);
    }
#pragma unroll
    for (int r = 0; r < 8; r++) {
        float inv = 1.0f / den[r];
        float a0, a1, a2, a3;
        unpack2(a0, a1, acc[r][0]);
        unpack2(a2, a3, acc[r][1]);
        float4 o;
        o.x = eluf(a0 * inv);
        o.y = eluf(a1 * inv);
        o.z = eluf(a2 * inv);
        o.w = eluf(a3 * inv);
        *(float4*)&d_gates[g][(n0 + r) * DD + lane * 4] = o;
    }
}

// ---------------- LSTM cell update ----------------
__global__ void k_cell() {
    int idx = blockIdx.x * blockDim.x + threadIdx.x;
    if (idx >= NN * DD) return;
    float g0 = d_gates[0][idx], g1 = d_gates[1][idx];
    float g2 = d_gates[2][idx], g3 = d_gates[3][idx];
    float fg = 1.f / (1.f + expf(-g0));
    float ig = 1.f / (1.f + expf(-g1));
    float cc = tanhf(g2);
    float og = 1.f / (1.f + expf(-g3));
    float c = d_cell[idx] * fg + ig * cc;
    d_cell[idx] = c;
    d_hidden[idx] = tanhf(c) * og;
}

// ---------------- outs[t] = sigmoid(hidden @ W + b) ----------------
__global__ __launch_bounds__(256) void k_out(const float* __restrict__ W,
                                             const float* __restrict__ bb, int t) {
    __shared__ __align__(16) float As[16][68];
    __shared__ __align__(16) float Bs[16][68];
    int tid = threadIdx.x;
    int n0  = blockIdx.x * 64;
    int d0  = blockIdx.y * 64;
    int tx  = tid & 15, ty = tid >> 4;
    float acc[4][4] = {};
    int la_n = tid >> 2;
    int la_k = (tid & 3) * 4;
    int lb_k = tid >> 4;
    int lb_d = (tid & 15) * 4;
    for (int k0 = 0; k0 < 128; k0 += 16) {
        __syncthreads();
        float4 av = *(const float4*)&d_hidden[(n0 + la_n) * DD + k0 + la_k];
        As[la_k + 0][la_n] = av.x; As[la_k + 1][la_n] = av.y;
        As[la_k + 2][la_n] = av.z; As[la_k + 3][la_n] = av.w;
        *(float4*)&Bs[lb_k][lb_d] = *(const float4*)&W[(k0 + lb_k) * DD + d0 + lb_d];
        __syncthreads();
#pragma unroll
        for (int kk = 0; kk < 16; kk++) {
            float4 a = *(float4*)&As[kk][ty * 4];
            float4 b = *(float4*)&Bs[kk][tx * 4];
            float ar[4] = {a.x, a.y, a.z, a.w};
            float br[4] = {b.x, b.y, b.z, b.w};
#pragma unroll
            for (int i = 0; i < 4; i++)
#pragma unroll
                for (int j = 0; j < 4; j++) acc[i][j] = fmaf(ar[i], br[j], acc[i][j]);
        }
    }
#pragma unroll
    for (int i = 0; i < 4; i++) {
        int row = n0 + ty * 4 + i;
#pragma unroll
        for (int j = 0; j < 4; j++) {
            float v = acc[i][j] + bb[d0 + tx * 4 + j];
            d_outs[t][row * DD + d0 + tx * 4 + j] = 1.f / (1.f + expf(-v));
        }
    }
}

// ---------------- conv layer: GEMM over k = s*128+c ----------------
__global__ __launch_bounds__(256) void k_conv(int l, const float* __restrict__ convb,
                                              float* __restrict__ outp) {
    __shared__ __align__(16) float As[16][68];
    __shared__ __align__(16) float Bs[16][68];
    const float* src;
    float* dst;
    if (l == 0)      { src = &d_outs[0][0]; dst = &d_y1[0][0]; }
    else if (l == 1) { src = &d_y1[0][0];   dst = &d_y2[0][0]; }
    else             { src = &d_y2[0][0];   dst = outp; }
    int tid  = threadIdx.x;
    int n0   = blockIdx.x * 64;
    int d0   = (blockIdx.y & 1) * 64;
    int tout = blockIdx.y >> 1;
    src += (size_t)tout * NN * DD;
    dst += (size_t)tout * NN * DD;
    int tx  = tid & 15, ty = tid >> 4;
    float acc[4][4] = {};
    int la_n = tid >> 2;
    int la_k = (tid & 3) * 4;
    int lb_k = tid >> 4;
    int lb_d = (tid & 15) * 4;
    for (int k0 = 0; k0 < 256; k0 += 16) {
        __syncthreads();
        int f = k0 + la_k;
        int s = f >> 7, c = f & 127;
        float4 av = *(const float4*)&src[(size_t)s * NN * DD + (n0 + la_n) * DD + c];
        As[la_k + 0][la_n] = av.x; As[la_k + 1][la_n] = av.y;
        As[la_k + 2][la_n] = av.z; As[la_k + 3][la_n] = av.w;
        *(float4*)&Bs[lb_k][lb_d] = *(const float4*)&d_convwT[l][k0 + lb_k][d0 + lb_d];
        __syncthreads();
#pragma unroll
        for (int kk = 0; kk < 16; kk++) {
            float4 a = *(float4*)&As[kk][ty * 4];
            float4 b = *(float4*)&Bs[kk][tx * 4];
            float ar[4] = {a.x, a.y, a.z, a.w};
            float br[4] = {b.x, b.y, b.z, b.w};
#pragma unroll
            for (int i = 0; i < 4; i++)
#pragma unroll
                for (int j = 0; j < 4; j++) acc[i][j] = fmaf(ar[i], br[j], acc[i][j]);
        }
    }
#pragma unroll
    for (int i = 0; i < 4; i++) {
        int row = n0 + ty * 4 + i;
#pragma unroll
        for (int j = 0; j < 4; j++) {
            int o = d0 + tx * 4 + j;
            dst[row * DD + o] = acc[i][j] + convb[l * 128 + o];
        }
    }
}

extern "C" void kernel_launch(void* const* d_in, const int* in_sizes, int n_in,
                              void* d_out, int out_size) {
    const float* actors = (const float*)d_in[0];
    const int*   G      = (const int*)d_in[1];
    const float* Wg     = (const float*)d_in[2];
    const float* ag     = (const float*)d_in[3];
    const float* W      = (const float*)d_in[4];
    const float* b      = (const float*)d_in[5];
    const float* h0     = (const float*)d_in[6];
    const float* convw  = (const float*)d_in[7];
    const float* convb  = (const float*)d_in[8];
    float* out = (float*)d_out;

    k_init<<<1024, 256>>>(actors, h0);
    k_pack<<<65536, 256>>>(G);
    k_transposeW<<<384, 256>>>(convw);

    for (int t = 0; t < 4; t++) {
        k_wh<<<dim3(32, 8), 256>>>(actors, Wg, t);
        k_prep<<<1024, 256>>>(ag);
        k_attn<<<dim3(64, 4), 128>>>(t);
        k_cell<<<1024, 256>>>();
        k_out<<<dim3(32, 2), 256>>>(W, b, t);
    }

    k_conv<<<dim3(32, 6), 256>>>(0, convb, out);
    k_conv<<<dim3(32, 4), 256>>>(1, convb, out);
    k_conv<<<dim3(32, 2), 256>>>(2, convb, out);
}

// round 5
// speedup vs baseline: 1.2446x; 1.2446x over previous
#include <cuda_runtime.h>
#include <cuda_bf16.h>
#include <math.h>
#include <stdint.h>

#define NN 2048
#define DD 128

__constant__ int c_xidx[4] = {4, 9, 14, 19};
__constant__ int c_eidx[4] = {0, 4, 9, 14};

// ---------------- static device scratch ----------------
__device__ unsigned d_bitmask[4][NN][64];
__device__ float    d_Wh[4][NN][DD];
__device__ float4   d_rowinfo[4][NN];
__device__ float4   d_colinfo[4][NN];
__device__ float    d_gates[4][NN * DD];
__device__ float    d_cell[NN * DD];
__device__ float    d_hidden[NN * DD];
__device__ float    d_outs[4][NN * DD];
__device__ float    d_y1[3][NN * DD];
__device__ float    d_y2[2][NN * DD];
__device__ float    d_convwT[3][256][DD];
__device__ __nv_bfloat16 d_WhT_hi[4][DD][NN];   // [g][d][m]
__device__ __nv_bfloat16 d_WhT_lo[4][DD][NN];

// ---------------- helpers ----------------
__device__ __forceinline__ float eluf(float x) { return x > 0.f ? x : expm1f(x); }

__device__ __forceinline__ void mma16816(float* c, const unsigned* a, const unsigned* b) {
    asm volatile("mma.sync.aligned.m16n8k16.row.col.f32.bf16.bf16.f32 "
        "{%0,%1,%2,%3}, {%4,%5,%6,%7}, {%8,%9}, {%0,%1,%2,%3};"
        : "+f"(c[0]), "+f"(c[1]), "+f"(c[2]), "+f"(c[3])
        : "r"(a[0]), "r"(a[1]), "r"(a[2]), "r"(a[3]), "r"(b[0]), "r"(b[1]));
}
__device__ __forceinline__ unsigned packbf(__nv_bfloat16 lo, __nv_bfloat16 hi) {
    return ((unsigned)__bfloat16_as_ushort(hi) << 16) | __bfloat16_as_ushort(lo);
}

// ---------------- init ----------------
__global__ void k_init(const float* __restrict__ actors, const float* __restrict__ h0) {
    int idx = blockIdx.x * blockDim.x + threadIdx.x;
    if (idx >= NN * DD) return;
    int n = idx >> 7, dd = idx & 127;
    d_cell[idx]   = actors[(size_t)n * 20 * DD + dd];
    d_hidden[idx] = h0[dd];
}

// ---------------- pack adjacency bitmasks ----------------
__global__ void k_pack(const int* __restrict__ G) {
    int wid  = (blockIdx.x * blockDim.x + threadIdx.x) >> 5;
    int lane = threadIdx.x & 31;
    int word = wid & 63;
    int n    = (wid >> 6) & (NN - 1);
    int t    = wid >> 17;
    int e    = c_eidx[t];
    int m    = (word << 5) + lane;
    int v    = G[(size_t)n * 20 * NN + (size_t)e * NN + m];
    unsigned b = __ballot_sync(0xffffffffu, v > 0);
    if (lane == 0) d_bitmask[t][n][word] = b;
}

// ---------------- conv weight transpose ----------------
__global__ void k_transposeW(const float* __restrict__ convw) {
    int idx = blockIdx.x * blockDim.x + threadIdx.x;
    if (idx >= 3 * 256 * DD) return;
    int o = idx & 127;
    int k = (idx >> 7) & 255;
    int l = idx >> 15;
    int c = k & 127, s = k >> 7;
    d_convwT[l][k][o] = convw[(((size_t)l * 128 + o) * 128 + c) * 2 + s];
}

// ---------------- Wh = [X_t | hidden] @ Wg ----------------
__global__ __launch_bounds__(256) void k_wh(const float* __restrict__ actors,
                                            const float* __restrict__ Wg, int t) {
    __shared__ __align__(16) float As[16][68];
    __shared__ __align__(16) float Bs[16][68];
    int tid = threadIdx.x;
    int n0  = blockIdx.x * 64;
    int g   = blockIdx.y >> 1;
    int d0  = (blockIdx.y & 1) * 64;
    int tx  = tid & 15, ty = tid >> 4;
    float acc[4][4] = {};
    int xoff = c_xidx[t] * DD;
    int la_n = tid >> 2;
    int la_k = (tid & 3) * 4;
    int lb_k = tid >> 4;
    int lb_d = (tid & 15) * 4;
    for (int k0 = 0; k0 < 256; k0 += 16) {
        __syncthreads();
        int f = k0 + la_k;
        float4 av;
        if (f < 128) av = *(const float4*)&actors[(size_t)(n0 + la_n) * 2560 + xoff + f];
        else         av = *(const float4*)&d_hidden[(n0 + la_n) * DD + f - 128];
        As[la_k + 0][la_n] = av.x; As[la_k + 1][la_n] = av.y;
        As[la_k + 2][la_n] = av.z; As[la_k + 3][la_n] = av.w;
        *(float4*)&Bs[lb_k][lb_d] =
            *(const float4*)&Wg[((size_t)g * 256 + k0 + lb_k) * DD + d0 + lb_d];
        __syncthreads();
#pragma unroll
        for (int kk = 0; kk < 16; kk++) {
            float4 a = *(float4*)&As[kk][ty * 4];
            float4 b = *(float4*)&Bs[kk][tx * 4];
            float ar[4] = {a.x, a.y, a.z, a.w};
            float br[4] = {b.x, b.y, b.z, b.w};
#pragma unroll
            for (int i = 0; i < 4; i++)
#pragma unroll
                for (int j = 0; j < 4; j++) acc[i][j] = fmaf(ar[i], br[j], acc[i][j]);
        }
    }
#pragma unroll
    for (int i = 0; i < 4; i++) {
        int row = n0 + ty * 4 + i;
        float4 o = make_float4(acc[i][0], acc[i][1], acc[i][2], acc[i][3]);
        *(float4*)&d_Wh[g][row][d0 + tx * 4] = o;
    }
}

// ---------------- Wh transpose + bf16 hi/lo split ----------------
__global__ void k_split() {
    __shared__ float tile[32][33];
    int m0 = blockIdx.x * 32, d0 = blockIdx.y * 32, g = blockIdx.z;
    int tx = threadIdx.x, ty = threadIdx.y;
#pragma unroll
    for (int i = 0; i < 4; i++)
        tile[ty + i * 8][tx] = d_Wh[g][m0 + ty + i * 8][d0 + tx];
    __syncthreads();
#pragma unroll
    for (int i = 0; i < 4; i++) {
        int drow = d0 + ty + i * 8;
        float v = tile[tx][ty + i * 8];
        __nv_bfloat16 h = __float2bfloat16(v);
        d_WhT_hi[g][drow][m0 + tx] = h;
        d_WhT_lo[g][drow][m0 + tx] = __float2bfloat16(v - __bfloat162float(h));
    }
}

// ---------------- per-(g,n) scores + factorized exps ----------------
__global__ void k_prep(const float* __restrict__ ag) {
    int gid  = (blockIdx.x * blockDim.x + threadIdx.x) >> 5;
    int lane = threadIdx.x & 31;
    int g = gid >> 11, n = gid & 2047;
    float4 wv = *(const float4*)&d_Wh[g][n][lane * 4];
    float4 as = *(const float4*)&ag[g * 256 + lane * 4];
    float4 ad = *(const float4*)&ag[g * 256 + 128 + lane * 4];
    float s1 = wv.x * as.x + wv.y * as.y + wv.z * as.z + wv.w * as.w;
    float s2 = wv.x * ad.x + wv.y * ad.y + wv.z * ad.z + wv.w * ad.w;
#pragma unroll
    for (int off = 16; off; off >>= 1) {
        s1 += __shfl_xor_sync(0xffffffffu, s1, off);
        s2 += __shfl_xor_sync(0xffffffffu, s2, off);
    }
    if (lane == 0) {
        d_rowinfo[g][n] = make_float4(-s1, expf(s1), expf(0.2f * s1), 0.f);
        d_colinfo[g][n] = make_float4(s2, expf(s2), expf(0.2f * s2), 0.f);
    }
}

// ---------------- tensor-core attention via mma.sync (sm_80 path) ----------------
// Block 128 thr / 4 warps: 64 rows x 128 d per (gate). m chunked by 32.
// out[n,d] = sum_m coef(n,m) * Wh[m,d]; coef split bf16 hi/lo, Wh split hi/lo,
// 3-term product for ~1e-5 accuracy. Denominator exact fp32.
__global__ __launch_bounds__(128) void k_attn_mma(int t) {
    __shared__ __align__(16) __nv_bfloat16 sAh[64][40], sAl[64][40];
    __shared__ __align__(16) __nv_bfloat16 sBh[128][40], sBl[128][40];
    __shared__ float4 sCol[32];
    __shared__ float  sDen[64];
    const int tid = threadIdx.x, wid = tid >> 5, lane = tid & 31;
    const int g   = blockIdx.y;
    const int n0  = blockIdx.x * 64;
    const int r   = tid >> 1, seg = tid & 1;      // coef mapping: row r, m-half seg
    const int gq  = lane >> 2, tq = lane & 3;     // fragment mapping

    const float4 ri = d_rowinfo[g][n0 + r];
    const unsigned* bm = &d_bitmask[t][n0 + r][0];
    float den = 0.f;
    float acc[16][4] = {};

    for (int c = 0; c < 64; c++) {
        const int m0 = c * 32;
        __syncthreads();
        // stage B (WhT hi/lo): thread tid owns d-row tid, 32 m values
        {
            const __nv_bfloat16* srcH = &d_WhT_hi[g][tid][m0];
            const __nv_bfloat16* srcL = &d_WhT_lo[g][tid][m0];
#pragma unroll
            for (int i = 0; i < 4; i++) {
                *(uint4*)&sBh[tid][i * 8] = *(const uint4*)&srcH[i * 8];
                *(uint4*)&sBl[tid][i * 8] = *(const uint4*)&srcL[i * 8];
            }
        }
        if (tid < 32) sCol[tid] = d_colinfo[g][m0 + tid];
        __syncthreads();

        // coef tile 64x32 -> bf16 hi/lo in sA
        {
            unsigned w = bm[c];
#pragma unroll
            for (int u = 0; u < 8; u++) {
                int j0 = seg * 16 + u * 2;
                float4 c0 = sCol[j0];
                float4 c1 = sCol[j0 + 1];
                float v0 = (c0.x >= ri.x) ? ri.y * c0.y : ri.z * c0.z;
                float v1 = (c1.x >= ri.x) ? ri.y * c1.y : ri.z * c1.z;
                float cf0 = ((w >> j0) & 1u) ? v0 : 0.f;
                float cf1 = ((w >> (j0 + 1)) & 1u) ? v1 : 0.f;
                den += cf0 + cf1;
                __nv_bfloat16 h0 = __float2bfloat16(cf0);
                __nv_bfloat16 h1 = __float2bfloat16(cf1);
                __nv_bfloat16 l0 = __float2bfloat16(cf0 - __bfloat162float(h0));
                __nv_bfloat16 l1 = __float2bfloat16(cf1 - __bfloat162float(h1));
                *(unsigned*)&sAh[r][j0] = packbf(h0, h1);
                *(unsigned*)&sAl[r][j0] = packbf(l0, l1);
            }
        }
        __syncthreads();

        // A fragments for this warp's 16 rows (both k-chunks)
        unsigned afh[2][4], afl[2][4];
#pragma unroll
        for (int kc = 0; kc < 2; kc++) {
            int mb = kc * 16 + 2 * tq;
            int ra = 16 * wid + gq;
            afh[kc][0] = *(unsigned*)&sAh[ra][mb];
            afh[kc][1] = *(unsigned*)&sAh[ra + 8][mb];
            afh[kc][2] = *(unsigned*)&sAh[ra][mb + 8];
            afh[kc][3] = *(unsigned*)&sAh[ra + 8][mb + 8];
            afl[kc][0] = *(unsigned*)&sAl[ra][mb];
            afl[kc][1] = *(unsigned*)&sAl[ra + 8][mb];
            afl[kc][2] = *(unsigned*)&sAl[ra][mb + 8];
            afl[kc][3] = *(unsigned*)&sAl[ra + 8][mb + 8];
        }
#pragma unroll
        for (int j = 0; j < 16; j++) {
            int drow = j * 8 + gq;
#pragma unroll
            for (int kc = 0; kc < 2; kc++) {
                int mb = kc * 16 + 2 * tq;
                unsigned bh[2], bl[2];
                bh[0] = *(unsigned*)&sBh[drow][mb];
                bh[1] = *(unsigned*)&sBh[drow][mb + 8];
                bl[0] = *(unsigned*)&sBl[drow][mb];
                bl[1] = *(unsigned*)&sBl[drow][mb + 8];
                mma16816(acc[j], afh[kc], bh);
                mma16816(acc[j], afh[kc], bl);
                mma16816(acc[j], afl[kc], bh);
            }
        }
    }

    // denominator: pair-reduce (tid, tid^1 share row r)
    den += __shfl_xor_sync(0xffffffffu, den, 1);
    if (seg == 0) sDen[r] = den;
    __syncthreads();

    float dinv0 = 1.f / sDen[16 * wid + gq];
    float dinv1 = 1.f / sDen[16 * wid + gq + 8];
    int row0 = n0 + 16 * wid + gq;
    int row1 = row0 + 8;
#pragma unroll
    for (int j = 0; j < 16; j++) {
        int dcol = j * 8 + 2 * tq;
        d_gates[g][row0 * DD + dcol]     = eluf(acc[j][0] * dinv0);
        d_gates[g][row0 * DD + dcol + 1] = eluf(acc[j][1] * dinv0);
        d_gates[g][row1 * DD + dcol]     = eluf(acc[j][2] * dinv1);
        d_gates[g][row1 * DD + dcol + 1] = eluf(acc[j][3] * dinv1);
    }
}

// ---------------- LSTM cell update ----------------
__global__ void k_cell() {
    int idx = blockIdx.x * blockDim.x + threadIdx.x;
    if (idx >= NN * DD) return;
    float g0 = d_gates[0][idx], g1 = d_gates[1][idx];
    float g2 = d_gates[2][idx], g3 = d_gates[3][idx];
    float fg = 1.f / (1.f + expf(-g0));
    float ig = 1.f / (1.f + expf(-g1));
    float cc = tanhf(g2);
    float og = 1.f / (1.f + expf(-g3));
    float c = d_cell[idx] * fg + ig * cc;
    d_cell[idx] = c;
    d_hidden[idx] = tanhf(c) * og;
}

// ---------------- outs[t] = sigmoid(hidden @ W + b) ----------------
__global__ __launch_bounds__(256) void k_out(const float* __restrict__ W,
                                             const float* __restrict__ bb, int t) {
    __shared__ __align__(16) float As[16][68];
    __shared__ __align__(16) float Bs[16][68];
    int tid = threadIdx.x;
    int n0  = blockIdx.x * 64;
    int d0  = blockIdx.y * 64;
    int tx  = tid & 15, ty = tid >> 4;
    float acc[4][4] = {};
    int la_n = tid >> 2;
    int la_k = (tid & 3) * 4;
    int lb_k = tid >> 4;
    int lb_d = (tid & 15) * 4;
    for (int k0 = 0; k0 < 128; k0 += 16) {
        __syncthreads();
        float4 av = *(const float4*)&d_hidden[(n0 + la_n) * DD + k0 + la_k];
        As[la_k + 0][la_n] = av.x; As[la_k + 1][la_n] = av.y;
        As[la_k + 2][la_n] = av.z; As[la_k + 3][la_n] = av.w;
        *(float4*)&Bs[lb_k][lb_d] = *(const float4*)&W[(k0 + lb_k) * DD + d0 + lb_d];
        __syncthreads();
#pragma unroll
        for (int kk = 0; kk < 16; kk++) {
            float4 a = *(float4*)&As[kk][ty * 4];
            float4 b = *(float4*)&Bs[kk][tx * 4];
            float ar[4] = {a.x, a.y, a.z, a.w};
            float br[4] = {b.x, b.y, b.z, b.w};
#pragma unroll
            for (int i = 0; i < 4; i++)
#pragma unroll
                for (int j = 0; j < 4; j++) acc[i][j] = fmaf(ar[i], br[j], acc[i][j]);
        }
    }
#pragma unroll
    for (int i = 0; i < 4; i++) {
        int row = n0 + ty * 4 + i;
#pragma unroll
        for (int j = 0; j < 4; j++) {
            float v = acc[i][j] + bb[d0 + tx * 4 + j];
            d_outs[t][row * DD + d0 + tx * 4 + j] = 1.f / (1.f + expf(-v));
        }
    }
}

// ---------------- conv layer ----------------
__global__ __launch_bounds__(256) void k_conv(int l, const float* __restrict__ convb,
                                              float* __restrict__ outp) {
    __shared__ __align__(16) float As[16][68];
    __shared__ __align__(16) float Bs[16][68];
    const float* src;
    float* dst;
    if (l == 0)      { src = &d_outs[0][0]; dst = &d_y1[0][0]; }
    else if (l == 1) { src = &d_y1[0][0];   dst = &d_y2[0][0]; }
    else             { src = &d_y2[0][0];   dst = outp; }
    int tid  = threadIdx.x;
    int n0   = blockIdx.x * 64;
    int d0   = (blockIdx.y & 1) * 64;
    int tout = blockIdx.y >> 1;
    src += (size_t)tout * NN * DD;
    dst += (size_t)tout * NN * DD;
    int tx  = tid & 15, ty = tid >> 4;
    float acc[4][4] = {};
    int la_n = tid >> 2;
    int la_k = (tid & 3) * 4;
    int lb_k = tid >> 4;
    int lb_d = (tid & 15) * 4;
    for (int k0 = 0; k0 < 256; k0 += 16) {
        __syncthreads();
        int f = k0 + la_k;
        int s = f >> 7, c = f & 127;
        float4 av = *(const float4*)&src[(size_t)s * NN * DD + (n0 + la_n) * DD + c];
        As[la_k + 0][la_n] = av.x; As[la_k + 1][la_n] = av.y;
        As[la_k + 2][la_n] = av.z; As[la_k + 3][la_n] = av.w;
        *(float4*)&Bs[lb_k][lb_d] = *(const float4*)&d_convwT[l][k0 + lb_k][d0 + lb_d];
        __syncthreads();
#pragma unroll
        for (int kk = 0; kk < 16; kk++) {
            float4 a = *(float4*)&As[kk][ty * 4];
            float4 b = *(float4*)&Bs[kk][tx * 4];
            float ar[4] = {a.x, a.y, a.z, a.w};
            float br[4] = {b.x, b.y, b.z, b.w};
#pragma unroll
            for (int i = 0; i < 4; i++)
#pragma unroll
                for (int j = 0; j < 4; j++) acc[i][j] = fmaf(ar[i], br[j], acc[i][j]);
        }
    }
#pragma unroll
    for (int i = 0; i < 4; i++) {
        int row = n0 + ty * 4 + i;
#pragma unroll
        for (int j = 0; j < 4; j++) {
            int o = d0 + tx * 4 + j;
            dst[row * DD + o] = acc[i][j] + convb[l * 128 + o];
        }
    }
}

extern "C" void kernel_launch(void* const* d_in, const int* in_sizes, int n_in,
                              void* d_out, int out_size) {
    const float* actors = (const float*)d_in[0];
    const int*   G      = (const int*)d_in[1];
    const float* Wg     = (const float*)d_in[2];
    const float* ag     = (const float*)d_in[3];
    const float* W      = (const float*)d_in[4];
    const float* b      = (const float*)d_in[5];
    const float* h0     = (const float*)d_in[6];
    const float* convw  = (const float*)d_in[7];
    const float* convb  = (const float*)d_in[8];
    float* out = (float*)d_out;

    k_init<<<1024, 256>>>(actors, h0);
    k_pack<<<65536, 256>>>(G);
    k_transposeW<<<384, 256>>>(convw);

    for (int t = 0; t < 4; t++) {
        k_wh<<<dim3(32, 8), 256>>>(actors, Wg, t);
        k_split<<<dim3(64, 4, 4), dim3(32, 8)>>>();
        k_prep<<<1024, 256>>>(ag);
        k_attn_mma<<<dim3(32, 4), 128>>>(t);
        k_cell<<<1024, 256>>>();
        k_out<<<dim3(32, 2), 256>>>(W, b, t);
    }

    k_conv<<<dim3(32, 6), 256>>>(0, convb, out);
    k_conv<<<dim3(32, 4), 256>>>(1, convb, out);
    k_conv<<<dim3(32, 2), 256>>>(2, convb, out);
}

// round 6
// speedup vs baseline: 1.6274x; 1.3076x over previous
#include <cuda_runtime.h>
#include <cuda_bf16.h>
#include <math.h>
#include <stdint.h>

#define NN 2048
#define DD 128

__constant__ int c_xidx[4] = {4, 9, 14, 19};
__constant__ int c_eidx[4] = {0, 4, 9, 14};

// ---------------- static device scratch ----------------
__device__ unsigned d_bitmask[4][NN][64];
__device__ float    d_Wh[4][NN][DD];
__device__ float4   d_rowinfo[4][NN];
__device__ float4   d_colinfo[4][NN];
__device__ float    d_gates[4][NN * DD];
__device__ float    d_cell[NN * DD];
__device__ float    d_hidden[NN * DD];
__device__ float    d_outs[4][NN * DD];
__device__ float    d_y1[3][NN * DD];
__device__ float    d_y2[2][NN * DD];
__device__ float    d_convwT[3][256][DD];
__device__ __nv_bfloat16 d_WhT_hi[4][DD][NN];   // [g][d][m]
__device__ __nv_bfloat16 d_WhT_lo[4][DD][NN];

// ---------------- helpers ----------------
__device__ __forceinline__ float eluf(float x) { return x > 0.f ? x : expm1f(x); }

__device__ __forceinline__ void mma16816(float* c, const unsigned* a, const unsigned* b) {
    asm volatile("mma.sync.aligned.m16n8k16.row.col.f32.bf16.bf16.f32 "
        "{%0,%1,%2,%3}, {%4,%5,%6,%7}, {%8,%9}, {%0,%1,%2,%3};"
        : "+f"(c[0]), "+f"(c[1]), "+f"(c[2]), "+f"(c[3])
        : "r"(a[0]), "r"(a[1]), "r"(a[2]), "r"(a[3]), "r"(b[0]), "r"(b[1]));
}
__device__ __forceinline__ unsigned packbf(__nv_bfloat16 lo, __nv_bfloat16 hi) {
    return ((unsigned)__bfloat16_as_ushort(hi) << 16) | __bfloat16_as_ushort(lo);
}
__device__ __forceinline__ void cpasync16(unsigned dst, const void* src) {
    asm volatile("cp.async.cg.shared.global [%0], [%1], 16;" :: "r"(dst), "l"(src));
}
#define CP_COMMIT() asm volatile("cp.async.commit_group;" ::: "memory")
#define CP_WAIT0()  asm volatile("cp.async.wait_group 0;" ::: "memory")

// ---------------- init ----------------
__global__ void k_init(const float* __restrict__ actors, const float* __restrict__ h0) {
    int idx = blockIdx.x * blockDim.x + threadIdx.x;
    if (idx >= NN * DD) return;
    int n = idx >> 7, dd = idx & 127;
    d_cell[idx]   = actors[(size_t)n * 20 * DD + dd];
    d_hidden[idx] = h0[dd];
}

// ---------------- pack adjacency bitmasks ----------------
__global__ void k_pack(const int* __restrict__ G) {
    int wid  = (blockIdx.x * blockDim.x + threadIdx.x) >> 5;
    int lane = threadIdx.x & 31;
    int word = wid & 63;
    int n    = (wid >> 6) & (NN - 1);
    int t    = wid >> 17;
    int e    = c_eidx[t];
    int m    = (word << 5) + lane;
    int v    = G[(size_t)n * 20 * NN + (size_t)e * NN + m];
    unsigned b = __ballot_sync(0xffffffffu, v > 0);
    if (lane == 0) d_bitmask[t][n][word] = b;
}

// ---------------- conv weight transpose ----------------
__global__ void k_transposeW(const float* __restrict__ convw) {
    int idx = blockIdx.x * blockDim.x + threadIdx.x;
    if (idx >= 3 * 256 * DD) return;
    int o = idx & 127;
    int k = (idx >> 7) & 255;
    int l = idx >> 15;
    int c = k & 127, s = k >> 7;
    d_convwT[l][k][o] = convw[(((size_t)l * 128 + o) * 128 + c) * 2 + s];
}

// ---------------- Wh = [X_t | hidden] @ Wg ----------------
__global__ __launch_bounds__(256) void k_wh(const float* __restrict__ actors,
                                            const float* __restrict__ Wg, int t) {
    __shared__ __align__(16) float As[16][68];
    __shared__ __align__(16) float Bs[16][68];
    int tid = threadIdx.x;
    int n0  = blockIdx.x * 64;
    int g   = blockIdx.y >> 1;
    int d0  = (blockIdx.y & 1) * 64;
    int tx  = tid & 15, ty = tid >> 4;
    float acc[4][4] = {};
    int xoff = c_xidx[t] * DD;
    int la_n = tid >> 2;
    int la_k = (tid & 3) * 4;
    int lb_k = tid >> 4;
    int lb_d = (tid & 15) * 4;
    for (int k0 = 0; k0 < 256; k0 += 16) {
        __syncthreads();
        int f = k0 + la_k;
        float4 av;
        if (f < 128) av = *(const float4*)&actors[(size_t)(n0 + la_n) * 2560 + xoff + f];
        else         av = *(const float4*)&d_hidden[(n0 + la_n) * DD + f - 128];
        As[la_k + 0][la_n] = av.x; As[la_k + 1][la_n] = av.y;
        As[la_k + 2][la_n] = av.z; As[la_k + 3][la_n] = av.w;
        *(float4*)&Bs[lb_k][lb_d] =
            *(const float4*)&Wg[((size_t)g * 256 + k0 + lb_k) * DD + d0 + lb_d];
        __syncthreads();
#pragma unroll
        for (int kk = 0; kk < 16; kk++) {
            float4 a = *(float4*)&As[kk][ty * 4];
            float4 b = *(float4*)&Bs[kk][tx * 4];
            float ar[4] = {a.x, a.y, a.z, a.w};
            float br[4] = {b.x, b.y, b.z, b.w};
#pragma unroll
            for (int i = 0; i < 4; i++)
#pragma unroll
                for (int j = 0; j < 4; j++) acc[i][j] = fmaf(ar[i], br[j], acc[i][j]);
        }
    }
#pragma unroll
    for (int i = 0; i < 4; i++) {
        int row = n0 + ty * 4 + i;
        float4 o = make_float4(acc[i][0], acc[i][1], acc[i][2], acc[i][3]);
        *(float4*)&d_Wh[g][row][d0 + tx * 4] = o;
    }
}

// ---------------- Wh transpose + bf16 hi/lo split ----------------
__global__ void k_split() {
    __shared__ float tile[32][33];
    int m0 = blockIdx.x * 32, d0 = blockIdx.y * 32, g = blockIdx.z;
    int tx = threadIdx.x, ty = threadIdx.y;
#pragma unroll
    for (int i = 0; i < 4; i++)
        tile[ty + i * 8][tx] = d_Wh[g][m0 + ty + i * 8][d0 + tx];
    __syncthreads();
#pragma unroll
    for (int i = 0; i < 4; i++) {
        int drow = d0 + ty + i * 8;
        float v = tile[tx][ty + i * 8];
        __nv_bfloat16 h = __float2bfloat16(v);
        d_WhT_hi[g][drow][m0 + tx] = h;
        d_WhT_lo[g][drow][m0 + tx] = __float2bfloat16(v - __bfloat162float(h));
    }
}

// ---------------- per-(g,n) scores + factorized exps ----------------
__global__ void k_prep(const float* __restrict__ ag) {
    int gid  = (blockIdx.x * blockDim.x + threadIdx.x) >> 5;
    int lane = threadIdx.x & 31;
    int g = gid >> 11, n = gid & 2047;
    float4 wv = *(const float4*)&d_Wh[g][n][lane * 4];
    float4 as = *(const float4*)&ag[g * 256 + lane * 4];
    float4 ad = *(const float4*)&ag[g * 256 + 128 + lane * 4];
    float s1 = wv.x * as.x + wv.y * as.y + wv.z * as.z + wv.w * as.w;
    float s2 = wv.x * ad.x + wv.y * ad.y + wv.z * ad.z + wv.w * ad.w;
#pragma unroll
    for (int off = 16; off; off >>= 1) {
        s1 += __shfl_xor_sync(0xffffffffu, s1, off);
        s2 += __shfl_xor_sync(0xffffffffu, s2, off);
    }
    if (lane == 0) {
        d_rowinfo[g][n] = make_float4(-s1, expf(s1), expf(0.2f * s1), 0.f);
        d_colinfo[g][n] = make_float4(s2, expf(s2), expf(0.2f * s2), 0.f);
    }
}

// ---------------- tensor-core attention: 8 warps, chunk 64, cp.async dbuf ----------
// Block 256 thr: 64 rows x 128 d. Warp w: rows 16*(w&3), d-half (w>>2)*64.
// smem layout (bytes, stride 144 = 72 bf16 per row):
//   B tiles: 2 bufs x {hi,lo} x 128 rows x 144    = 73728
//   Col:     2 bufs x 64 x 16                     = 2048
//   A tiles: {hi,lo} x 64 rows x 144              = 18432
//   Den:     64 x 4                               = 256
#define OFF_B   0
#define OFF_COL 73728
#define OFF_A   75776
#define OFF_DEN 94208
#define ATTN_SMEM 94464
#define BSTRIDE 144

__global__ __launch_bounds__(256) void k_attn_mma(int t) {
    extern __shared__ __align__(16) char smem[];
    const unsigned sbase = (unsigned)__cvta_generic_to_shared(smem);
    const int tid  = threadIdx.x;
    const int lane = tid & 31;
    const int warp = tid >> 5;
    const int rg   = warp & 3;        // row group (16 rows)
    const int dh   = warp >> 2;       // d half
    const int gq   = lane >> 2, tq = lane & 3;
    const int g    = blockIdx.y;
    const int n0   = blockIdx.x * 64;

    // staging ids: thread copies d-row srow, m-half sseg (32 elems = 64 B)
    const int srow = tid >> 1, sseg = tid & 1;
    // coef ids: row r, m-quarter seg (16 m)
    const int r = tid >> 2, seg = tid & 3;

    const float4 ri = d_rowinfo[g][n0 + r];
    const unsigned* bmrow = &d_bitmask[t][n0 + r][0];
    const __nv_bfloat16* gH = &d_WhT_hi[g][srow][sseg * 32];
    const __nv_bfloat16* gL = &d_WhT_lo[g][srow][sseg * 32];

    float4* sCol = (float4*)(smem + OFF_COL);
    float*  sDen = (float*)(smem + OFF_DEN);
    __nv_bfloat16* sA = (__nv_bfloat16*)(smem + OFF_A);

    // prefetch chunk 0 into buf 0
    {
        unsigned dh2 = sbase + OFF_B + (unsigned)srow * BSTRIDE + sseg * 64;
        unsigned dl2 = dh2 + 128 * BSTRIDE;
#pragma unroll
        for (int i = 0; i < 4; i++) {
            cpasync16(dh2 + i * 16, (const char*)gH + i * 16);
            cpasync16(dl2 + i * 16, (const char*)gL + i * 16);
        }
        if (tid < 64)
            cpasync16(sbase + OFF_COL + tid * 16, &d_colinfo[g][tid]);
        CP_COMMIT();
    }

    float acc[8][4] = {};
    float den = 0.f;

    for (int c = 0; c < 32; c++) {
        const int buf = c & 1;
        CP_WAIT0();
        __syncthreads();

        // prefetch chunk c+1 into other buffer
        if (c + 1 < 32) {
            const int nb = buf ^ 1;
            unsigned dh2 = sbase + OFF_B + (unsigned)(nb * 2 * 128 + srow) * BSTRIDE + sseg * 64;
            unsigned dl2 = dh2 + 128 * BSTRIDE;
            const char* sH = (const char*)(gH + (c + 1) * 64);
            const char* sL = (const char*)(gL + (c + 1) * 64);
#pragma unroll
            for (int i = 0; i < 4; i++) {
                cpasync16(dh2 + i * 16, sH + i * 16);
                cpasync16(dl2 + i * 16, sL + i * 16);
            }
            if (tid < 64)
                cpasync16(sbase + OFF_COL + (nb * 64 + tid) * 16,
                          &d_colinfo[g][(c + 1) * 64 + tid]);
            CP_COMMIT();
        }

        // ---- coef tile 64 x 64 -> sA hi/lo (16 coefs per thread) ----
        {
            unsigned w = bmrow[2 * c + (seg >> 1)];
            int bbase = (seg & 1) * 16;
            const float4* col = &sCol[buf * 64];
#pragma unroll
            for (int u = 0; u < 8; u++) {
                int j0 = seg * 16 + u * 2;
                float4 c0 = col[j0];
                float4 c1 = col[j0 + 1];
                float v0 = (c0.x >= ri.x) ? ri.y * c0.y : ri.z * c0.z;
                float v1 = (c1.x >= ri.x) ? ri.y * c1.y : ri.z * c1.z;
                float cf0 = ((w >> (bbase + 2 * u)) & 1u) ? v0 : 0.f;
                float cf1 = ((w >> (bbase + 2 * u + 1)) & 1u) ? v1 : 0.f;
                den += cf0 + cf1;
                __nv_bfloat16 h0 = __float2bfloat16(cf0);
                __nv_bfloat16 h1 = __float2bfloat16(cf1);
                __nv_bfloat16 l0 = __float2bfloat16(cf0 - __bfloat162float(h0));
                __nv_bfloat16 l1 = __float2bfloat16(cf1 - __bfloat162float(h1));
                *(unsigned*)((char*)sA + r * BSTRIDE + j0 * 2) = packbf(h0, h1);
                *(unsigned*)((char*)sA + (64 + r) * BSTRIDE + j0 * 2) = packbf(l0, l1);
            }
        }
        __syncthreads();

        // ---- MMA: warp computes rows [16*rg, +16), d [dh*64, +64) ----
        unsigned afh[4][4], afl[4][4];
        {
            const char* a0 = (char*)sA + (16 * rg + gq) * BSTRIDE;
            const char* a1 = a0 + 8 * BSTRIDE;
            const char* b0 = a0 + 64 * BSTRIDE;
            const char* b1 = a1 + 64 * BSTRIDE;
#pragma unroll
            for (int kc = 0; kc < 4; kc++) {
                int mb = (kc * 16 + 2 * tq) * 2;
                afh[kc][0] = *(const unsigned*)(a0 + mb);
                afh[kc][1] = *(const unsigned*)(a1 + mb);
                afh[kc][2] = *(const unsigned*)(a0 + mb + 16);
                afh[kc][3] = *(const unsigned*)(a1 + mb + 16);
                afl[kc][0] = *(const unsigned*)(b0 + mb);
                afl[kc][1] = *(const unsigned*)(b1 + mb);
                afl[kc][2] = *(const unsigned*)(b0 + mb + 16);
                afl[kc][3] = *(const unsigned*)(b1 + mb + 16);
            }
        }
        const char* bhBase = smem + OFF_B + (size_t)(buf * 2) * 128 * BSTRIDE;
        const char* blBase = bhBase + 128 * BSTRIDE;
#pragma unroll
        for (int j = 0; j < 8; j++) {
            int drow = dh * 64 + j * 8 + gq;
            const char* ph = bhBase + drow * BSTRIDE;
            const char* pl = blBase + drow * BSTRIDE;
#pragma unroll
            for (int kc = 0; kc < 4; kc++) {
                int mb = (kc * 16 + 2 * tq) * 2;
                unsigned bh[2], bl[2];
                bh[0] = *(const unsigned*)(ph + mb);
                bh[1] = *(const unsigned*)(ph + mb + 16);
                bl[0] = *(const unsigned*)(pl + mb);
                bl[1] = *(const unsigned*)(pl + mb + 16);
                mma16816(acc[j], afh[kc], bh);
                mma16816(acc[j], afh[kc], bl);
                mma16816(acc[j], afl[kc], bh);
            }
        }
    }

    // denominator reduce: 4 threads (same r) hold disjoint m partials
    den += __shfl_xor_sync(0xffffffffu, den, 1);
    den += __shfl_xor_sync(0xffffffffu, den, 2);
    if ((tid & 3) == 0) sDen[r] = den;
    __syncthreads();

    float dinv0 = 1.f / sDen[16 * rg + gq];
    float dinv1 = 1.f / sDen[16 * rg + gq + 8];
    int row0 = n0 + 16 * rg + gq;
    int row1 = row0 + 8;
#pragma unroll
    for (int j = 0; j < 8; j++) {
        int dcol = dh * 64 + j * 8 + 2 * tq;
        d_gates[g][row0 * DD + dcol]     = eluf(acc[j][0] * dinv0);
        d_gates[g][row0 * DD + dcol + 1] = eluf(acc[j][1] * dinv0);
        d_gates[g][row1 * DD + dcol]     = eluf(acc[j][2] * dinv1);
        d_gates[g][row1 * DD + dcol + 1] = eluf(acc[j][3] * dinv1);
    }
}

// ---------------- LSTM cell update ----------------
__global__ void k_cell() {
    int idx = blockIdx.x * blockDim.x + threadIdx.x;
    if (idx >= NN * DD) return;
    float g0 = d_gates[0][idx], g1 = d_gates[1][idx];
    float g2 = d_gates[2][idx], g3 = d_gates[3][idx];
    float fg = 1.f / (1.f + expf(-g0));
    float ig = 1.f / (1.f + expf(-g1));
    float cc = tanhf(g2);
    float og = 1.f / (1.f + expf(-g3));
    float c = d_cell[idx] * fg + ig * cc;
    d_cell[idx] = c;
    d_hidden[idx] = tanhf(c) * og;
}

// ---------------- outs[t] = sigmoid(hidden @ W + b) ----------------
__global__ __launch_bounds__(256) void k_out(const float* __restrict__ W,
                                             const float* __restrict__ bb, int t) {
    __shared__ __align__(16) float As[16][68];
    __shared__ __align__(16) float Bs[16][68];
    int tid = threadIdx.x;
    int n0  = blockIdx.x * 64;
    int d0  = blockIdx.y * 64;
    int tx  = tid & 15, ty = tid >> 4;
    float acc[4][4] = {};
    int la_n = tid >> 2;
    int la_k = (tid & 3) * 4;
    int lb_k = tid >> 4;
    int lb_d = (tid & 15) * 4;
    for (int k0 = 0; k0 < 128; k0 += 16) {
        __syncthreads();
        float4 av = *(const float4*)&d_hidden[(n0 + la_n) * DD + k0 + la_k];
        As[la_k + 0][la_n] = av.x; As[la_k + 1][la_n] = av.y;
        As[la_k + 2][la_n] = av.z; As[la_k + 3][la_n] = av.w;
        *(float4*)&Bs[lb_k][lb_d] = *(const float4*)&W[(k0 + lb_k) * DD + d0 + lb_d];
        __syncthreads();
#pragma unroll
        for (int kk = 0; kk < 16; kk++) {
            float4 a = *(float4*)&As[kk][ty * 4];
            float4 b = *(float4*)&Bs[kk][tx * 4];
            float ar[4] = {a.x, a.y, a.z, a.w};
            float br[4] = {b.x, b.y, b.z, b.w};
#pragma unroll
            for (int i = 0; i < 4; i++)
#pragma unroll
                for (int j = 0; j < 4; j++) acc[i][j] = fmaf(ar[i], br[j], acc[i][j]);
        }
    }
#pragma unroll
    for (int i = 0; i < 4; i++) {
        int row = n0 + ty * 4 + i;
#pragma unroll
        for (int j = 0; j < 4; j++) {
            float v = acc[i][j] + bb[d0 + tx * 4 + j];
            d_outs[t][row * DD + d0 + tx * 4 + j] = 1.f / (1.f + expf(-v));
        }
    }
}

// ---------------- conv layer ----------------
__global__ __launch_bounds__(256) void k_conv(int l, const float* __restrict__ convb,
                                              float* __restrict__ outp) {
    __shared__ __align__(16) float As[16][68];
    __shared__ __align__(16) float Bs[16][68];
    const float* src;
    float* dst;
    if (l == 0)      { src = &d_outs[0][0]; dst = &d_y1[0][0]; }
    else if (l == 1) { src = &d_y1[0][0];   dst = &d_y2[0][0]; }
    else             { src = &d_y2[0][0];   dst = outp; }
    int tid  = threadIdx.x;
    int n0   = blockIdx.x * 64;
    int d0   = (blockIdx.y & 1) * 64;
    int tout = blockIdx.y >> 1;
    src += (size_t)tout * NN * DD;
    dst += (size_t)tout * NN * DD;
    int tx  = tid & 15, ty = tid >> 4;
    float acc[4][4] = {};
    int la_n = tid >> 2;
    int la_k = (tid & 3) * 4;
    int lb_k = tid >> 4;
    int lb_d = (tid & 15) * 4;
    for (int k0 = 0; k0 < 256; k0 += 16) {
        __syncthreads();
        int f = k0 + la_k;
        int s = f >> 7, c = f & 127;
        float4 av = *(const float4*)&src[(size_t)s * NN * DD + (n0 + la_n) * DD + c];
        As[la_k + 0][la_n] = av.x; As[la_k + 1][la_n] = av.y;
        As[la_k + 2][la_n] = av.z; As[la_k + 3][la_n] = av.w;
        *(float4*)&Bs[lb_k][lb_d] = *(const float4*)&d_convwT[l][k0 + lb_k][d0 + lb_d];
        __syncthreads();
#pragma unroll
        for (int kk = 0; kk < 16; kk++) {
            float4 a = *(float4*)&As[kk][ty * 4];
            float4 b = *(float4*)&Bs[kk][tx * 4];
            float ar[4] = {a.x, a.y, a.z, a.w};
            float br[4] = {b.x, b.y, b.z, b.w};
#pragma unroll
            for (int i = 0; i < 4; i++)
#pragma unroll
                for (int j = 0; j < 4; j++) acc[i][j] = fmaf(ar[i], br[j], acc[i][j]);
        }
    }
#pragma unroll
    for (int i = 0; i < 4; i++) {
        int row = n0 + ty * 4 + i;
#pragma unroll
        for (int j = 0; j < 4; j++) {
            int o = d0 + tx * 4 + j;
            dst[row * DD + o] = acc[i][j] + convb[l * 128 + o];
        }
    }
}

extern "C" void kernel_launch(void* const* d_in, const int* in_sizes, int n_in,
                              void* d_out, int out_size) {
    const float* actors = (const float*)d_in[0];
    const int*   G      = (const int*)d_in[1];
    const float* Wg     = (const float*)d_in[2];
    const float* ag     = (const float*)d_in[3];
    const float* W      = (const float*)d_in[4];
    const float* b      = (const float*)d_in[5];
    const float* h0     = (const float*)d_in[6];
    const float* convw  = (const float*)d_in[7];
    const float* convb  = (const float*)d_in[8];
    float* out = (float*)d_out;

    static int smem_set = 0;
    if (!smem_set) {
        cudaFuncSetAttribute(k_attn_mma, cudaFuncAttributeMaxDynamicSharedMemorySize,
                             ATTN_SMEM);
        smem_set = 1;
    }

    k_init<<<1024, 256>>>(actors, h0);
    k_pack<<<65536, 256>>>(G);
    k_transposeW<<<384, 256>>>(convw);

    for (int t = 0; t < 4; t++) {
        k_wh<<<dim3(32, 8), 256>>>(actors, Wg, t);
        k_split<<<dim3(64, 4, 4), dim3(32, 8)>>>();
        k_prep<<<1024, 256>>>(ag);
        k_attn_mma<<<dim3(32, 4), 256, ATTN_SMEM>>>(t);
        k_cell<<<1024, 256>>>();
        k_out<<<dim3(32, 2), 256>>>(W, b, t);
    }

    k_conv<<<dim3(32, 6), 256>>>(0, convb, out);
    k_conv<<<dim3(32, 4), 256>>>(1, convb, out);
    k_conv<<<dim3(32, 2), 256>>>(2, convb, out);
}